// round 16
// baseline (speedup 1.0000x reference)
#include <cuda_runtime.h>
#include <cuda_fp16.h>
#include <stdint.h>
#include <math.h>

#define BB    4
#define TSEQ  2048
#define DM    1024
#define DI    2048
#define DS_   16
#define DTR   64
#define FFND  3584
#define MROWS (BB*TSEQ)   // 8192
#define NC    32
#define CL    64

// ---------------- static device scratch -----------------------------------
__device__ float  g_X  [MROWS*DM];       // residual stream (fp32)
__device__ __half g_Xn [MROWS*DM];       // LN output
__device__ __half g_xz [MROWS*2*DI];     // in_proj output (half)
__device__ __half g_xc [MROWS*DI];       // conv+silu output
__device__ __half g_xd [MROWS*96];       // x_proj output (dt|B|C)
__device__ __half g_dt [MROWS*DI];       // softplus(dt) (half)
__device__ __half g_ym [MROWS*DI];       // gated scan output
__device__ __half g_ffn[MROWS*FFND];     // ffn hidden
__device__ float  g_cP [BB*NC*DI*DS_];
__device__ float  g_cS [BB*NC*DI*DS_];
__device__ float  g_cI [BB*NC*DI*DS_];
__device__ __half g_wa [56*1024*1024];   // all weights, f16

// weight scratch offsets (halves)
#define OW_IN   0
#define SZ_IN   (4*2*DI*DM)
#define OW_XP   (OW_IN + SZ_IN)
#define SZ_XP   (4*96*DI)
#define OW_DT   (OW_XP + SZ_XP)
#define SZ_DT   (4*DI*DTR)
#define OW_OUT  (OW_DT + SZ_DT)
#define SZ_OUT  (4*DM*DI)
#define OW_F1   (OW_OUT + SZ_OUT)
#define SZ_F1   (4*FFND*DM)
#define OW_F2   (OW_F1 + SZ_F1)
#define SZ_F2   (4*DM*FFND)

// ---------------- helpers ---------------------------------------------------
__device__ __forceinline__ void cpasync16(uint32_t dst, const void* src) {
    asm volatile("cp.async.cg.shared.global [%0], [%1], 16;" :: "r"(dst), "l"(src));
}
#define LDSM4(r0, r1, r2, r3, a) \
    asm volatile("ldmatrix.sync.aligned.m8n8.x4.shared.b16 {%0,%1,%2,%3}, [%4];" \
        : "=r"(r0), "=r"(r1), "=r"(r2), "=r"(r3) : "r"(a))
__device__ __forceinline__ void mma_f16(float c[4], uint32_t a0, uint32_t a1,
                                        uint32_t a2, uint32_t a3,
                                        uint32_t b0, uint32_t b1) {
    asm volatile(
        "mma.sync.aligned.m16n8k16.row.col.f32.f16.f16.f32 "
        "{%0,%1,%2,%3}, {%4,%5,%6,%7}, {%8,%9}, {%0,%1,%2,%3};"
        : "+f"(c[0]), "+f"(c[1]), "+f"(c[2]), "+f"(c[3])
        : "r"(a0), "r"(a1), "r"(a2), "r"(a3), "r"(b0), "r"(b1));
}
__device__ __forceinline__ uint2 cvt4(float4 v) {
    __half2 h0 = __floats2half2_rn(v.x, v.y);
    __half2 h1 = __floats2half2_rn(v.z, v.w);
    return make_uint2(*(uint32_t*)&h0, *(uint32_t*)&h1);
}

// ---------------- epilogue (shared by GEMM kernels) ----------------------
// epi: 2:Ch=gelu(v+b) 3:Cf+=v 5:Ch=softplus(v+b) 6:Ch=v 7:Cf=(Cf+v+b)*mask(+out2)
__device__ __forceinline__ void epi_pair(
    float v0, float v1, int r, int cn, int ldc, int N, int epi,
    float* Cf, __half* Ch, const float* bias, const int* lenp, float* out2) {
    if (cn >= N) return;
    if (epi == 2) {
        float u0 = v0 + bias[cn], u1 = v1 + bias[cn + 1];
        float g0 = 0.5f * u0 * (1.0f + erff(u0 * 0.70710678118654752f));
        float g1 = 0.5f * u1 * (1.0f + erff(u1 * 0.70710678118654752f));
        *(__half2*)(Ch + (size_t)r * ldc + cn) = __floats2half2_rn(g0, g1);
    } else if (epi == 3) {
        Cf[(size_t)r * ldc + cn]     += v0;
        Cf[(size_t)r * ldc + cn + 1] += v1;
    } else if (epi == 5) {
        float u0 = v0 + bias[cn], u1 = v1 + bias[cn + 1];
        u0 = (u0 > 20.f) ? u0 : __logf(1.0f + __expf(u0));
        u1 = (u1 > 20.f) ? u1 : __logf(1.0f + __expf(u1));
        *(__half2*)(Ch + (size_t)r * ldc + cn) = __floats2half2_rn(u0, u1);
    } else if (epi == 6) {
        *(__half2*)(Ch + (size_t)r * ldc + cn) = __floats2half2_rn(v0, v1);
    } else { // 7
        int t = r & (TSEQ - 1), bidx = r >> 11;
        float o0 = Cf[(size_t)r * ldc + cn]     + v0 + bias[cn];
        float o1 = Cf[(size_t)r * ldc + cn + 1] + v1 + bias[cn + 1];
        if (t >= lenp[bidx]) { o0 = 0.f; o1 = 0.f; }
        Cf[(size_t)r * ldc + cn]     = o0;
        Cf[(size_t)r * ldc + cn + 1] = o1;
        if (out2) {
            out2[(size_t)r * ldc + cn]     = o0;
            out2[(size_t)r * ldc + cn + 1] = o1;
        }
    }
}

// ---------------- weight convert f32 -> f16 ---------------------------------
__global__ void k_round(const float* __restrict__ in, __half* __restrict__ out, int n4) {
    int i = blockIdx.x * 256 + threadIdx.x;
    if (i < n4) ((uint2*)out)[i] = cvt4(((const float4*)in)[i]);
}
__global__ void k_round5(
    const float* __restrict__ a, __half* __restrict__ oa, int na,
    const float* __restrict__ b, __half* __restrict__ ob, int nb,
    const float* __restrict__ c, __half* __restrict__ oc, int ncnt,
    const float* __restrict__ d, __half* __restrict__ od, int nd,
    const float* __restrict__ e, __half* __restrict__ oe, int ne) {
    int i = blockIdx.x * 256 + threadIdx.x;
    const float* s; __half* o;
    if (i < na) { s = a; o = oa; }
    else { i -= na;
      if (i < nb) { s = b; o = ob; }
      else { i -= nb;
        if (i < ncnt) { s = c; o = oc; }
        else { i -= ncnt;
          if (i < nd) { s = d; o = od; }
          else { i -= nd; if (i >= ne) return; s = e; o = oe; } } } }
    ((uint2*)o)[i] = cvt4(((const float4*)s)[i]);
}

// ---------------- block reduce ----------------------------------------------
__device__ __forceinline__ float blockReduce(float v, float* sh) {
    int lane = threadIdx.x & 31, wid = threadIdx.x >> 5;
    #pragma unroll
    for (int o = 16; o > 0; o >>= 1) v += __shfl_down_sync(0xffffffffu, v, o);
    if (lane == 0) sh[wid] = v;
    __syncthreads();
    if (threadIdx.x == 0) {
        float s = 0.f;
        #pragma unroll
        for (int i = 0; i < 8; i++) s += sh[i];
        sh[32] = s;
    }
    __syncthreads();
    float r = sh[32];
    __syncthreads();
    return r;
}

// ---------------- fused PE + ln0 + ln1(->half) --------------------------------
__global__ __launch_bounds__(256) void k_peln2(
    const float* __restrict__ xin, float* __restrict__ X, __half* __restrict__ Xn,
    const float* __restrict__ g0, const float* __restrict__ b0,
    const float* __restrict__ g1, const float* __restrict__ b1) {
    __shared__ float sh[33];
    int row = blockIdx.x;
    int t = row & (TSEQ - 1);
    int c = threadIdx.x * 4;
    float4 v = ((const float4*)(xin + (size_t)row * DM))[threadIdx.x];
    float pv[4];
    #pragma unroll
    for (int j = 0; j < 4; j++) {
        int d = c + j;
        float freq = expf((float)(d & ~1) * (-9.210340371976184f / (float)DM));
        float ang = (float)t * freq;
        pv[j] = (d & 1) ? cosf(ang) : sinf(ang);
    }
    v.x += pv[0]; v.y += pv[1]; v.z += pv[2]; v.w += pv[3];
    float mean = blockReduce(v.x + v.y + v.z + v.w, sh) * (1.0f / DM);
    float dx = v.x - mean, dy = v.y - mean, dz = v.z - mean, dw = v.w - mean;
    float var = blockReduce(dx*dx + dy*dy + dz*dz + dw*dw, sh) * (1.0f / DM);
    float rstd = rsqrtf(var + 1e-5f);
    float4 o;
    o.x = dx * rstd * g0[c + 0] + b0[c + 0];
    o.y = dy * rstd * g0[c + 1] + b0[c + 1];
    o.z = dz * rstd * g0[c + 2] + b0[c + 2];
    o.w = dw * rstd * g0[c + 3] + b0[c + 3];
    ((float4*)(X + (size_t)row * DM))[threadIdx.x] = o;
    float m2 = blockReduce(o.x + o.y + o.z + o.w, sh) * (1.0f / DM);
    float ex = o.x - m2, ey = o.y - m2, ez = o.z - m2, ew = o.w - m2;
    float v2 = blockReduce(ex*ex + ey*ey + ez*ez + ew*ew, sh) * (1.0f / DM);
    float r2 = rsqrtf(v2 + 1e-5f);
    float4 q;
    q.x = ex * r2 * g1[c + 0] + b1[c + 0];
    q.y = ey * r2 * g1[c + 1] + b1[c + 1];
    q.z = ez * r2 * g1[c + 2] + b1[c + 2];
    q.w = ew * r2 * g1[c + 3] + b1[c + 3];
    ((uint2*)(Xn + (size_t)row * DM))[threadIdx.x] = cvt4(q);
}

// ---------------- layernorm (fp32 in, half out) --------------------------------
__global__ __launch_bounds__(256) void k_ln_h(const float* __restrict__ in,
                                              __half* __restrict__ out,
                                              const float* __restrict__ g,
                                              const float* __restrict__ b) {
    __shared__ float sh[33];
    int row = blockIdx.x;
    float4 v = ((const float4*)(in + (size_t)row * DM))[threadIdx.x];
    float mean = blockReduce(v.x + v.y + v.z + v.w, sh) * (1.0f / DM);
    float dx = v.x - mean, dy = v.y - mean, dz = v.z - mean, dw = v.w - mean;
    float var = blockReduce(dx*dx + dy*dy + dz*dz + dw*dw, sh) * (1.0f / DM);
    float rstd = rsqrtf(var + 1e-5f);
    int c = threadIdx.x * 4;
    float4 q;
    q.x = dx * rstd * g[c + 0] + b[c + 0];
    q.y = dy * rstd * g[c + 1] + b[c + 1];
    q.z = dz * rstd * g[c + 2] + b[c + 2];
    q.w = dw * rstd * g[c + 3] + b[c + 3];
    ((uint2*)(out + (size_t)row * DM))[threadIdx.x] = cvt4(q);
}

// ---------------- GEMM kernel A: 128x128, 256 thr ----------------------------
#define SROWH 40                           // halves per smem row (80 B)
#define ABUF  (128 * SROWH * 2)            // 10240 B
#define NSTG  5
#define SMEMA (2 * NSTG * ABUF)            // 102400 B

__global__ __launch_bounds__(256, 2) void k_gemm_tc(
    const __half* __restrict__ A, const __half* __restrict__ W,
    float* __restrict__ Cf, __half* __restrict__ Ch, const float* __restrict__ bias,
    const int* __restrict__ lenp, float* __restrict__ out2,
    int N, int K, int lda, int ldw, int ldc, int epi) {
    extern __shared__ __half smh[];
    const int tid = threadIdx.x;
    const int lane = tid & 31;
    const int wid = tid >> 5;
    const int wm = wid & 1, wn = wid >> 1;
    const int g = lane >> 2, tig = lane & 3;
    const int bM = blockIdx.y * 128, bN = blockIdx.x * 128;

    const int lrow = tid >> 1;
    const int lc0 = (tid & 1) << 1;
    const __half* Ag = A + (size_t)(bM + lrow) * lda;
    int wr = bN + lrow; if (wr >= N) wr = N - 1;
    const __half* Wg = W + (size_t)wr * ldw;

    const uint32_t sA = (uint32_t)__cvta_generic_to_shared(smh);
    const uint32_t sB = sA + NSTG * ABUF;
    const uint32_t dRow = (uint32_t)lrow * (SROWH * 2);

    const uint32_t aoff = (uint32_t)((wm * 64 + (lane & 15)) * (SROWH * 2) + ((lane >> 4) << 4));
    const uint32_t boff = (uint32_t)((wn * 32 + ((lane >> 4) << 3) + (lane & 7)) * (SROWH * 2)
                                     + (((lane >> 3) & 1) << 4));

    float acc[4][4][4];
    #pragma unroll
    for (int i = 0; i < 4; i++)
        #pragma unroll
        for (int j = 0; j < 4; j++)
            #pragma unroll
            for (int q = 0; q < 4; q++) acc[i][j][q] = 0.f;

    const int KT = K / 32;
    #pragma unroll
    for (int s = 0; s < 3; s++) {
        if (s < KT) {
            const int k2 = s * 32;
            #pragma unroll
            for (int c = 0; c < 2; c++) {
                cpasync16(sA + s * ABUF + dRow + (lc0 + c) * 16, Ag + k2 + (lc0 + c) * 8);
                cpasync16(sB + s * ABUF + dRow + (lc0 + c) * 16, Wg + k2 + (lc0 + c) * 8);
            }
            asm volatile("cp.async.commit_group;");
        }
    }

    int s_r = 0, s_w = 3;
    for (int j = 0; j < KT; j++) {
        const int rem = KT - 1 - j;
        if (rem >= 3) {
            const int k2 = (j + 3) * 32;
            #pragma unroll
            for (int c = 0; c < 2; c++) {
                cpasync16(sA + s_w * ABUF + dRow + (lc0 + c) * 16, Ag + k2 + (lc0 + c) * 8);
                cpasync16(sB + s_w * ABUF + dRow + (lc0 + c) * 16, Wg + k2 + (lc0 + c) * 8);
            }
            asm volatile("cp.async.commit_group;");
            if (++s_w == NSTG) s_w = 0;
            asm volatile("cp.async.wait_group 3;");
        } else if (rem == 2) {
            asm volatile("cp.async.wait_group 2;");
        } else if (rem == 1) {
            asm volatile("cp.async.wait_group 1;");
        } else {
            asm volatile("cp.async.wait_group 0;");
        }
        __syncthreads();

        const uint32_t ab = sA + s_r * ABUF;
        const uint32_t bb = sB + s_r * ABUF;
        if (++s_r == NSTG) s_r = 0;
        #pragma unroll
        for (int ks = 0; ks < 2; ks++) {
            uint32_t af[4][4], bf[4][2];
            #pragma unroll
            for (int i = 0; i < 4; i++)
                LDSM4(af[i][0], af[i][1], af[i][2], af[i][3],
                      ab + aoff + (uint32_t)(i * 16 * SROWH * 2 + ks * 32));
            #pragma unroll
            for (int jp = 0; jp < 2; jp++)
                LDSM4(bf[2*jp][0], bf[2*jp][1], bf[2*jp+1][0], bf[2*jp+1][1],
                      bb + boff + (uint32_t)(jp * 16 * SROWH * 2 + ks * 32));
            #pragma unroll
            for (int i = 0; i < 4; i++)
                #pragma unroll
                for (int jj = 0; jj < 4; jj++)
                    mma_f16(acc[i][jj], af[i][0], af[i][1], af[i][2], af[i][3],
                            bf[jj][0], bf[jj][1]);
        }
    }

    #pragma unroll
    for (int i = 0; i < 4; i++) {
        const int r0 = bM + wm * 64 + i * 16 + g;
        #pragma unroll
        for (int j = 0; j < 4; j++) {
            const int cn = bN + wn * 32 + j * 8 + tig * 2;
            #pragma unroll
            for (int h = 0; h < 2; h++)
                epi_pair(acc[i][j][h*2], acc[i][j][h*2+1], r0 + h * 8, cn,
                         ldc, N, epi, Cf, Ch, bias, lenp, out2);
        }
    }
}

// ---------------- GEMM kernel B: 128x256, 512 thr (N % 256 == 0) -------------
#define ABUFA (128 * SROWH * 2)            // 10240 B
#define ABUFB (256 * SROWH * 2)            // 20480 B
#define NSTG2 5
#define SMEMB (NSTG2 * (ABUFA + ABUFB))    // 153600 B

__global__ __launch_bounds__(512, 1) void k_gemm_tc2(
    const __half* __restrict__ A, const __half* __restrict__ W,
    float* __restrict__ Cf, __half* __restrict__ Ch, const float* __restrict__ bias,
    const int* __restrict__ lenp, float* __restrict__ out2,
    int N, int K, int lda, int ldw, int ldc, int epi) {
    extern __shared__ __half smh[];
    const int tid = threadIdx.x;
    const int lane = tid & 31;
    const int wid = tid >> 5;                 // 0..15
    const int wm = wid & 1, wn = wid >> 1;    // 2 x 8 warps
    const int g = lane >> 2, tig = lane & 3;
    const int bM = blockIdx.y * 128, bN = blockIdx.x * 256;

    const int lrA = tid >> 2, lcA = tid & 3;
    const __half* Ag = A + (size_t)(bM + lrA) * lda;
    const int lrB = tid >> 1, lcB = (tid & 1) << 1;
    const __half* Wg = W + (size_t)(bN + lrB) * ldw;

    const uint32_t sA = (uint32_t)__cvta_generic_to_shared(smh);
    const uint32_t sB = sA + NSTG2 * ABUFA;
    const uint32_t dRowA = (uint32_t)lrA * (SROWH * 2);
    const uint32_t dRowB = (uint32_t)lrB * (SROWH * 2);

    const uint32_t aoff = (uint32_t)((wm * 64 + (lane & 15)) * (SROWH * 2) + ((lane >> 4) << 4));
    const uint32_t boff = (uint32_t)((wn * 32 + ((lane >> 4) << 3) + (lane & 7)) * (SROWH * 2)
                                     + (((lane >> 3) & 1) << 4));

    float acc[4][4][4];
    #pragma unroll
    for (int i = 0; i < 4; i++)
        #pragma unroll
        for (int j = 0; j < 4; j++)
            #pragma unroll
            for (int q = 0; q < 4; q++) acc[i][j][q] = 0.f;

    const int KT = K / 32;
    #pragma unroll
    for (int s = 0; s < 3; s++) {
        if (s < KT) {
            const int k2 = s * 32;
            cpasync16(sA + s * ABUFA + dRowA + lcA * 16, Ag + k2 + lcA * 8);
            #pragma unroll
            for (int c = 0; c < 2; c++)
                cpasync16(sB + s * ABUFB + dRowB + (lcB + c) * 16, Wg + k2 + (lcB + c) * 8);
            asm volatile("cp.async.commit_group;");
        }
    }

    int s_r = 0, s_w = 3;
    for (int j = 0; j < KT; j++) {
        const int rem = KT - 1 - j;
        if (rem >= 3) {
            const int k2 = (j + 3) * 32;
            cpasync16(sA + s_w * ABUFA + dRowA + lcA * 16, Ag + k2 + lcA * 8);
            #pragma unroll
            for (int c = 0; c < 2; c++)
                cpasync16(sB + s_w * ABUFB + dRowB + (lcB + c) * 16, Wg + k2 + (lcB + c) * 8);
            asm volatile("cp.async.commit_group;");
            if (++s_w == NSTG2) s_w = 0;
            asm volatile("cp.async.wait_group 3;");
        } else if (rem == 2) {
            asm volatile("cp.async.wait_group 2;");
        } else if (rem == 1) {
            asm volatile("cp.async.wait_group 1;");
        } else {
            asm volatile("cp.async.wait_group 0;");
        }
        __syncthreads();

        const uint32_t ab = sA + s_r * ABUFA;
        const uint32_t bb = sB + s_r * ABUFB;
        if (++s_r == NSTG2) s_r = 0;
        #pragma unroll
        for (int ks = 0; ks < 2; ks++) {
            uint32_t af[4][4], bf[4][2];
            #pragma unroll
            for (int i = 0; i < 4; i++)
                LDSM4(af[i][0], af[i][1], af[i][2], af[i][3],
                      ab + aoff + (uint32_t)(i * 16 * SROWH * 2 + ks * 32));
            #pragma unroll
            for (int jp = 0; jp < 2; jp++)
                LDSM4(bf[2*jp][0], bf[2*jp][1], bf[2*jp+1][0], bf[2*jp+1][1],
                      bb + boff + (uint32_t)(jp * 16 * SROWH * 2 + ks * 32));
            #pragma unroll
            for (int i = 0; i < 4; i++)
                #pragma unroll
                for (int jj = 0; jj < 4; jj++)
                    mma_f16(acc[i][jj], af[i][0], af[i][1], af[i][2], af[i][3],
                            bf[jj][0], bf[jj][1]);
        }
    }

    #pragma unroll
    for (int i = 0; i < 4; i++) {
        const int r0 = bM + wm * 64 + i * 16 + g;
        #pragma unroll
        for (int j = 0; j < 4; j++) {
            const int cn = bN + wn * 32 + j * 8 + tig * 2;
            #pragma unroll
            for (int h = 0; h < 2; h++)
                epi_pair(acc[i][j][h*2], acc[i][j][h*2+1], r0 + h * 8, cn,
                         ldc, N, epi, Cf, Ch, bias, lenp, out2);
        }
    }
}

// ---------------- GEMM kernel C: 64x128, 128 thr (xp GEMM, N=96) -------------
// M tile 64 doubles CTA count for the skinny xp projection (64 -> 128 CTAs).
#define ABUF3A (64 * SROWH * 2)            // 5120 B
#define ABUF3B (128 * SROWH * 2)           // 10240 B
#define NSTG3  5
#define SMEMC  (NSTG3 * (ABUF3A + ABUF3B)) // 76800 B

__global__ __launch_bounds__(128, 2) void k_gemm_tc3(
    const __half* __restrict__ A, const __half* __restrict__ W,
    float* __restrict__ Cf, __half* __restrict__ Ch, const float* __restrict__ bias,
    const int* __restrict__ lenp, float* __restrict__ out2,
    int N, int K, int lda, int ldw, int ldc, int epi) {
    extern __shared__ __half smh[];
    const int tid = threadIdx.x;
    const int lane = tid & 31;
    const int wid = tid >> 5;                 // 0..3, 1(m) x 4(n) warps of 64x32
    const int g = lane >> 2, tig = lane & 3;
    const int bM = blockIdx.y * 64, bN = blockIdx.x * 128;

    // A loaders: 2 threads/row (64 rows), 2 chunks each
    const int lrA = tid >> 1, lcA = (tid & 1) << 1;
    const __half* Ag = A + (size_t)(bM + lrA) * lda;
    // B loaders: 1 thread/row (128 rows), 4 chunks each
    int wr = bN + tid; if (wr >= N) wr = N - 1;
    const __half* Wg = W + (size_t)wr * ldw;

    const uint32_t sA = (uint32_t)__cvta_generic_to_shared(smh);
    const uint32_t sB = sA + NSTG3 * ABUF3A;
    const uint32_t dRowA = (uint32_t)lrA * (SROWH * 2);
    const uint32_t dRowB = (uint32_t)tid * (SROWH * 2);

    const uint32_t aoff = (uint32_t)((lane & 15) * (SROWH * 2) + ((lane >> 4) << 4));
    const uint32_t boff = (uint32_t)((wid * 32 + ((lane >> 4) << 3) + (lane & 7)) * (SROWH * 2)
                                     + (((lane >> 3) & 1) << 4));

    float acc[4][4][4];
    #pragma unroll
    for (int i = 0; i < 4; i++)
        #pragma unroll
        for (int j = 0; j < 4; j++)
            #pragma unroll
            for (int q = 0; q < 4; q++) acc[i][j][q] = 0.f;

    const int KT = K / 32;
    #pragma unroll
    for (int s = 0; s < 3; s++) {
        if (s < KT) {
            const int k2 = s * 32;
            #pragma unroll
            for (int c = 0; c < 2; c++)
                cpasync16(sA + s * ABUF3A + dRowA + (lcA + c) * 16, Ag + k2 + (lcA + c) * 8);
            #pragma unroll
            for (int c = 0; c < 4; c++)
                cpasync16(sB + s * ABUF3B + dRowB + c * 16, Wg + k2 + c * 8);
            asm volatile("cp.async.commit_group;");
        }
    }

    int s_r = 0, s_w = 3;
    for (int j = 0; j < KT; j++) {
        const int rem = KT - 1 - j;
        if (rem >= 3) {
            const int k2 = (j + 3) * 32;
            #pragma unroll
            for (int c = 0; c < 2; c++)
                cpasync16(sA + s_w * ABUF3A + dRowA + (lcA + c) * 16, Ag + k2 + (lcA + c) * 8);
            #pragma unroll
            for (int c = 0; c < 4; c++)
                cpasync16(sB + s_w * ABUF3B + dRowB + c * 16, Wg + k2 + c * 8);
            asm volatile("cp.async.commit_group;");
            if (++s_w == NSTG3) s_w = 0;
            asm volatile("cp.async.wait_group 3;");
        } else if (rem == 2) {
            asm volatile("cp.async.wait_group 2;");
        } else if (rem == 1) {
            asm volatile("cp.async.wait_group 1;");
        } else {
            asm volatile("cp.async.wait_group 0;");
        }
        __syncthreads();

        const uint32_t ab = sA + s_r * ABUF3A;
        const uint32_t bb = sB + s_r * ABUF3B;
        if (++s_r == NSTG3) s_r = 0;
        #pragma unroll
        for (int ks = 0; ks < 2; ks++) {
            uint32_t af[4][4], bf[4][2];
            #pragma unroll
            for (int i = 0; i < 4; i++)
                LDSM4(af[i][0], af[i][1], af[i][2], af[i][3],
                      ab + aoff + (uint32_t)(i * 16 * SROWH * 2 + ks * 32));
            #pragma unroll
            for (int jp = 0; jp < 2; jp++)
                LDSM4(bf[2*jp][0], bf[2*jp][1], bf[2*jp+1][0], bf[2*jp+1][1],
                      bb + boff + (uint32_t)(jp * 16 * SROWH * 2 + ks * 32));
            #pragma unroll
            for (int i = 0; i < 4; i++)
                #pragma unroll
                for (int jj = 0; jj < 4; jj++)
                    mma_f16(acc[i][jj], af[i][0], af[i][1], af[i][2], af[i][3],
                            bf[jj][0], bf[jj][1]);
        }
    }

    #pragma unroll
    for (int i = 0; i < 4; i++) {
        const int r0 = bM + i * 16 + g;
        #pragma unroll
        for (int j = 0; j < 4; j++) {
            const int cn = bN + wid * 32 + j * 8 + tig * 2;
            #pragma unroll
            for (int h = 0; h < 2; h++)
                epi_pair(acc[i][j][h*2], acc[i][j][h*2+1], r0 + h * 8, cn,
                         ldc, N, epi, Cf, Ch, bias, lenp, out2);
        }
    }
}

// ---------------- causal conv (k=4) + silu, 4 timesteps/thread ----------------
__global__ void k_conv(const __half* __restrict__ xz, const float* __restrict__ cw,
                       const float* __restrict__ cb, __half* __restrict__ xc) {
    int idx = blockIdx.x * 256 + threadIdx.x;    // over (MROWS/4)*(DI/2)
    int d2 = idx & (DI / 2 - 1);
    int mq = idx >> 10;
    int m0 = mq * 4;
    int t0 = m0 & (TSEQ - 1);
    int d = d2 * 2;
    float lo[7], hi[7];
    #pragma unroll
    for (int j = 0; j < 7; j++) {
        int tt = t0 - 3 + j;
        if (tt >= 0) {
            __half2 hv = *(const __half2*)(xz + (size_t)(m0 - 3 + j) * (2 * DI) + d);
            lo[j] = __low2float(hv); hi[j] = __high2float(hv);
        } else { lo[j] = 0.f; hi[j] = 0.f; }
    }
    float w0[4], w1[4];
    #pragma unroll
    for (int k = 0; k < 4; k++) { w0[k] = cw[d * 4 + k]; w1[k] = cw[(d + 1) * 4 + k]; }
    float b0 = cb[d], b1 = cb[d + 1];
    #pragma unroll
    for (int o = 0; o < 4; o++) {
        float a0 = b0, a1 = b1;
        #pragma unroll
        for (int k = 0; k < 4; k++) {
            a0 += lo[o + k] * w0[k];
            a1 += hi[o + k] * w1[k];
        }
        float s0 = a0 / (1.0f + __expf(-a0));
        float s1 = a1 / (1.0f + __expf(-a1));
        *(__half2*)(xc + (size_t)(m0 + o) * DI + d) = __floats2half2_rn(s0, s1);
    }
}

// ---------------- scan pass A -------------------------------------------------
__global__ __launch_bounds__(256) void k_scanA(
    const __half* __restrict__ dt, const __half* __restrict__ xc,
    const __half* __restrict__ xd, const float* __restrict__ Alog,
    float* __restrict__ gP, float* __restrict__ gS) {
    __shared__ float shB[CL][DS_];
    int b = blockIdx.z, c = blockIdx.y;
    int d = blockIdx.x * 256 + threadIdx.x;
    int mbase = b * TSEQ + c * CL;
    for (int idx = threadIdx.x; idx < CL * DS_; idx += 256) {
        int t = idx >> 4, col = idx & 15;
        shB[t][col] = __half2float(xd[(size_t)(mbase + t) * 96 + 64 + col]);
    }
    __syncthreads();
    float r[DS_];
    bool fast = true;
    #pragma unroll
    for (int n = 0; n < DS_; n++) {
        r[n] = expf(Alog[(size_t)d * DS_ + n]);
        fast = fast && (fabsf(r[n] - (float)(n + 1)) < 1e-3f * (float)(n + 1));
    }
    float P[DS_], S[DS_];
    #pragma unroll
    for (int n = 0; n < DS_; n++) { P[n] = 1.f; S[n] = 0.f; }
    for (int t = 0; t < CL; t++) {
        int m = mbase + t;
        float dv = __half2float(dt[(size_t)m * DI + d]);
        float xv = __half2float(xc[(size_t)m * DI + d]);
        float u = xv * dv;
        float dA[DS_];
        if (fast) {
            float e = __expf(-dv);
            float p = 1.f;
            #pragma unroll
            for (int n = 0; n < DS_; n++) { p *= e; dA[n] = p; }
        } else {
            #pragma unroll
            for (int n = 0; n < DS_; n++) dA[n] = __expf(-dv * r[n]);
        }
        #pragma unroll
        for (int n = 0; n < DS_; n++) {
            S[n] = S[n] * dA[n] + u * shB[t][n];
            P[n] *= dA[n];
        }
    }
    size_t base = (((size_t)b * NC + c) * DI + d) * DS_;
    #pragma unroll
    for (int n = 0; n < DS_; n += 4) {
        *(float4*)(gP + base + n) = make_float4(P[n], P[n+1], P[n+2], P[n+3]);
        *(float4*)(gS + base + n) = make_float4(S[n], S[n+1], S[n+2], S[n+3]);
    }
}

// ---------------- scan pass B (parallel over 4-state quads) -------------------
__global__ void k_scanB(const float* __restrict__ gP, const float* __restrict__ gS,
                        float* __restrict__ gI) {
    int idx = blockIdx.x * 256 + threadIdx.x;   // over BB*DI*4 = 32768
    int nq = (idx & 3) * 4;
    int d  = (idx >> 2) & (DI - 1);
    int b  = idx >> 13;
    float4 s = make_float4(0.f, 0.f, 0.f, 0.f);
    for (int c = 0; c < NC; c++) {
        size_t base = (((size_t)b * NC + c) * DI + d) * DS_ + nq;
        *(float4*)(gI + base) = s;
        float4 P = *(const float4*)(gP + base);
        float4 S = *(const float4*)(gS + base);
        s.x = s.x * P.x + S.x;
        s.y = s.y * P.y + S.y;
        s.z = s.z * P.z + S.z;
        s.w = s.w * P.w + S.w;
    }
}

// ---------------- scan pass C -------------------------------------------------
__global__ __launch_bounds__(256) void k_scanC(
    const __half* __restrict__ dt, const __half* __restrict__ xc,
    const __half* __restrict__ xd, const __half* __restrict__ xz,
    const float* __restrict__ Alog, const float* __restrict__ Dsk,
    const float* __restrict__ gI, __half* __restrict__ ym) {
    __shared__ float shB[CL][DS_];
    __shared__ float shC[CL][DS_];
    int b = blockIdx.z, c = blockIdx.y;
    int d = blockIdx.x * 256 + threadIdx.x;
    int mbase = b * TSEQ + c * CL;
    for (int idx = threadIdx.x; idx < CL * 32; idx += 256) {
        int t = idx >> 5, col = idx & 31;
        float v = __half2float(xd[(size_t)(mbase + t) * 96 + 64 + col]);
        if (col < 16) shB[t][col] = v;
        else shC[t][col - 16] = v;
    }
    __syncthreads();
    float r[DS_];
    bool fast = true;
    #pragma unroll
    for (int n = 0; n < DS_; n++) {
        r[n] = expf(Alog[(size_t)d * DS_ + n]);
        fast = fast && (fabsf(r[n] - (float)(n + 1)) < 1e-3f * (float)(n + 1));
    }
    float dskip = Dsk[d];
    float s[DS_];
    size_t base = (((size_t)b * NC + c) * DI + d) * DS_;
    #pragma unroll
    for (int n = 0; n < DS_; n += 4) {
        float4 v = *(const float4*)(gI + base + n);
        s[n+0] = v.x; s[n+1] = v.y; s[n+2] = v.z; s[n+3] = v.w;
    }
    for (int t = 0; t < CL; t++) {
        int m = mbase + t;
        float dv = __half2float(dt[(size_t)m * DI + d]);
        float xv = __half2float(xc[(size_t)m * DI + d]);
        float u = xv * dv;
        float dA[DS_];
        if (fast) {
            float e = __expf(-dv);
            float p = 1.f;
            #pragma unroll
            for (int n = 0; n < DS_; n++) { p *= e; dA[n] = p; }
        } else {
            #pragma unroll
            for (int n = 0; n < DS_; n++) dA[n] = __expf(-dv * r[n]);
        }
        float y = 0.f;
        #pragma unroll
        for (int n = 0; n < DS_; n++) {
            s[n] = s[n] * dA[n] + u * shB[t][n];
            y += s[n] * shC[t][n];
        }
        float z = __half2float(xz[(size_t)m * (2 * DI) + DI + d]);
        float sg = 1.0f / (1.0f + __expf(-z));
        ym[(size_t)m * DI + d] = __float2half_rn((y + dskip * xv) * (z * sg));
    }
}

// ---------------- host orchestration -------------------------------------------
static void launch_gemm(const __half* A, const __half* W,
                        float* Cf, __half* Ch, const float* bias,
                        const int* lenp, float* out2,
                        int N, int K, int lda, int ldc, int epi) {
    if ((N & 255) == 0) {
        dim3 grid(N / 256, MROWS / 128);
        k_gemm_tc2<<<grid, 512, SMEMB>>>(A, W, Cf, Ch, bias, lenp, out2, N, K, lda, K, ldc, epi);
    } else if (N <= 128) {
        dim3 grid(1, MROWS / 64);
        k_gemm_tc3<<<grid, 128, SMEMC>>>(A, W, Cf, Ch, bias, lenp, out2, N, K, lda, K, ldc, epi);
    } else {
        dim3 grid((N + 127) / 128, MROWS / 128);
        k_gemm_tc<<<grid, 256, SMEMA>>>(A, W, Cf, Ch, bias, lenp, out2, N, K, lda, K, ldc, epi);
    }
}

extern "C" void kernel_launch(void* const* d_in, const int* in_sizes, int n_in,
                              void* d_out, int out_size) {
    const float* x       = (const float*)d_in[0];
    const int*   lengths = (const int*)  d_in[1];
    const float* ln0_g   = (const float*)d_in[2];
    const float* ln0_b   = (const float*)d_in[3];
    const float* ln1_g   = (const float*)d_in[4];
    const float* ln1_b   = (const float*)d_in[5];
    const float* in_w    = (const float*)d_in[6];
    const float* conv_w  = (const float*)d_in[7];
    const float* conv_b  = (const float*)d_in[8];
    const float* xp_w    = (const float*)d_in[9];
    const float* dt_w    = (const float*)d_in[10];
    const float* dt_b    = (const float*)d_in[11];
    const float* A_log   = (const float*)d_in[12];
    const float* D_skip  = (const float*)d_in[13];
    const float* out_w   = (const float*)d_in[14];
    const float* ln2_g   = (const float*)d_in[15];
    const float* ln2_b   = (const float*)d_in[16];
    const float* f1_w    = (const float*)d_in[17];
    const float* f1_b    = (const float*)d_in[18];
    const float* f2_w    = (const float*)d_in[19];
    const float* f2_b    = (const float*)d_in[20];

    cudaFuncSetAttribute(k_gemm_tc,  cudaFuncAttributeMaxDynamicSharedMemorySize, SMEMA);
    cudaFuncSetAttribute(k_gemm_tc2, cudaFuncAttributeMaxDynamicSharedMemorySize, SMEMB);
    cudaFuncSetAttribute(k_gemm_tc3, cudaFuncAttributeMaxDynamicSharedMemorySize, SMEMC);

    float *pX, *pP, *pS, *pI;
    __half *pXn, *pXz, *pXc, *pXd, *pDt, *pY, *pF, *pWa;
    cudaGetSymbolAddress((void**)&pX,  g_X);
    cudaGetSymbolAddress((void**)&pXn, g_Xn);
    cudaGetSymbolAddress((void**)&pXz, g_xz);
    cudaGetSymbolAddress((void**)&pXc, g_xc);
    cudaGetSymbolAddress((void**)&pXd, g_xd);
    cudaGetSymbolAddress((void**)&pDt, g_dt);
    cudaGetSymbolAddress((void**)&pY,  g_ym);
    cudaGetSymbolAddress((void**)&pF,  g_ffn);
    cudaGetSymbolAddress((void**)&pP,  g_cP);
    cudaGetSymbolAddress((void**)&pS,  g_cS);
    cudaGetSymbolAddress((void**)&pI,  g_cI);
    cudaGetSymbolAddress((void**)&pWa, g_wa);

    // [1] in_proj weights
    k_round<<<(SZ_IN / 4 + 255) / 256, 256>>>(in_w, pWa + OW_IN, SZ_IN / 4);
    // [2] remaining weights, one packed launch
    {
        int na = SZ_XP / 4, nb = SZ_DT / 4, nc2 = SZ_OUT / 4, nd = SZ_F1 / 4, ne = SZ_F2 / 4;
        int tot = na + nb + nc2 + nd + ne;
        k_round5<<<(tot + 255) / 256, 256>>>(
            xp_w,  pWa + OW_XP,  na,
            dt_w,  pWa + OW_DT,  nb,
            out_w, pWa + OW_OUT, nc2,
            f1_w,  pWa + OW_F1,  nd,
            f2_w,  pWa + OW_F2,  ne);
    }
    // [3] fused PE + ln0 + ln1(layer0)
    k_peln2<<<MROWS, 256>>>(x, pX, pXn, ln0_g, ln0_b, ln1_g, ln1_b);

    for (int i = 0; i < 4; i++) {
        // --- Mamba block ---
        if (i > 0)
            k_ln_h<<<MROWS, 256>>>(pX, pXn, ln1_g + i * DM, ln1_b + i * DM);
        // [4] in_proj GEMM (ncu capture slot)
        launch_gemm(pXn, pWa + OW_IN + (size_t)i * 2 * DI * DM, nullptr, pXz, nullptr,
                    nullptr, nullptr, 2 * DI, DM, DM, 2 * DI, 6);
        k_conv<<<(MROWS / 4) * (DI / 2) / 256, 256>>>(pXz, conv_w + (size_t)i * DI * 4,
                                                      conv_b + (size_t)i * DI, pXc);
        launch_gemm(pXc, pWa + OW_XP + (size_t)i * 96 * DI, nullptr, pXd, nullptr,
                    nullptr, nullptr, 96, DI, DI, 96, 6);
        launch_gemm(pXd, pWa + OW_DT + (size_t)i * DI * DTR, nullptr, pDt,
                    dt_b + (size_t)i * DI, nullptr, nullptr, DI, DTR, 96, DI, 5);
        dim3 sg(DI / 256, NC, BB);
        k_scanA<<<sg, 256>>>(pDt, pXc, pXd, A_log + (size_t)i * DI * DS_, pP, pS);
        k_scanB<<<(BB * DI * 4) / 256, 256>>>(pP, pS, pI);
        k_scanC<<<sg, 256>>>(pDt, pXc, pXd, pXz, A_log + (size_t)i * DI * DS_,
                             D_skip + (size_t)i * DI, pI, pY);
        launch_gemm(pY, pWa + OW_OUT + (size_t)i * DM * DI, pX, nullptr, nullptr,
                    nullptr, nullptr, DM, DI, DI, DM, 3);
        // --- FFN block ---
        k_ln_h<<<MROWS, 256>>>(pX, pXn, ln2_g + i * DM, ln2_b + i * DM);
        launch_gemm(pXn, pWa + OW_F1 + (size_t)i * FFND * DM, nullptr, pF,
                    f1_b + (size_t)i * FFND, nullptr, nullptr, FFND, DM, DM, FFND, 2);
        launch_gemm(pF, pWa + OW_F2 + (size_t)i * DM * FFND, pX, nullptr,
                    f2_b + (size_t)i * DM, lengths,
                    (i == 3) ? (float*)d_out : nullptr, DM, FFND, FFND, DM, 7);
    }
}

// round 17
// speedup vs baseline: 1.0194x; 1.0194x over previous
#include <cuda_runtime.h>
#include <cuda_fp16.h>
#include <stdint.h>
#include <math.h>

#define BB    4
#define TSEQ  2048
#define DM    1024
#define DI    2048
#define DS_   16
#define DTR   64
#define FFND  3584
#define MROWS (BB*TSEQ)   // 8192
#define NC    32
#define CL    64

// ---------------- static device scratch -----------------------------------
__device__ float  g_X  [MROWS*DM];
__device__ __half g_Xn [MROWS*DM];
__device__ __half g_xz [MROWS*2*DI];
__device__ __half g_xc [MROWS*DI];
__device__ __half g_xd [MROWS*96];
__device__ __half g_dt [MROWS*DI];
__device__ __half g_ym [MROWS*DI];
__device__ __half g_ffn[MROWS*FFND];
__device__ float  g_cP [BB*NC*DI*DS_];
__device__ float  g_cS [BB*NC*DI*DS_];
__device__ float  g_cI [BB*NC*DI*DS_];
__device__ __half g_wa [56*1024*1024];

// weight scratch offsets (halves)
#define OW_IN   0
#define SZ_IN   (4*2*DI*DM)
#define OW_XP   (OW_IN + SZ_IN)
#define SZ_XP   (4*96*DI)
#define OW_DT   (OW_XP + SZ_XP)
#define SZ_DT   (4*DI*DTR)
#define OW_OUT  (OW_DT + SZ_DT)
#define SZ_OUT  (4*DM*DI)
#define OW_F1   (OW_OUT + SZ_OUT)
#define SZ_F1   (4*FFND*DM)
#define OW_F2   (OW_F1 + SZ_F1)
#define SZ_F2   (4*DM*FFND)

// ---------------- helpers ---------------------------------------------------
__device__ __forceinline__ void cpasync16(uint32_t dst, const void* src) {
    asm volatile("cp.async.cg.shared.global [%0], [%1], 16;" :: "r"(dst), "l"(src));
}
#define LDSM4(r0, r1, r2, r3, a) \
    asm volatile("ldmatrix.sync.aligned.m8n8.x4.shared.b16 {%0,%1,%2,%3}, [%4];" \
        : "=r"(r0), "=r"(r1), "=r"(r2), "=r"(r3) : "r"(a))
__device__ __forceinline__ void mma_f16(float c[4], uint32_t a0, uint32_t a1,
                                        uint32_t a2, uint32_t a3,
                                        uint32_t b0, uint32_t b1) {
    asm volatile(
        "mma.sync.aligned.m16n8k16.row.col.f32.f16.f16.f32 "
        "{%0,%1,%2,%3}, {%4,%5,%6,%7}, {%8,%9}, {%0,%1,%2,%3};"
        : "+f"(c[0]), "+f"(c[1]), "+f"(c[2]), "+f"(c[3])
        : "r"(a0), "r"(a1), "r"(a2), "r"(a3), "r"(b0), "r"(b1));
}
__device__ __forceinline__ uint2 cvt4(float4 v) {
    __half2 h0 = __floats2half2_rn(v.x, v.y);
    __half2 h1 = __floats2half2_rn(v.z, v.w);
    return make_uint2(*(uint32_t*)&h0, *(uint32_t*)&h1);
}

// ---------------- epilogue (shared) -------------------------------------------
// epi: 2:Ch=gelu(v+b) 3:Cf+=v 5:Ch=softplus(v+b) 6:Ch=v 7:Cf=(Cf+v+b)*mask(+out2)
__device__ __forceinline__ void epi_pair(
    float v0, float v1, int r, int cn, int ldc, int N, int epi,
    float* Cf, __half* Ch, const float* bias, const int* lenp, float* out2) {
    if (cn >= N) return;
    if (epi == 2) {
        float u0 = v0 + bias[cn], u1 = v1 + bias[cn + 1];
        float g0 = 0.5f * u0 * (1.0f + erff(u0 * 0.70710678118654752f));
        float g1 = 0.5f * u1 * (1.0f + erff(u1 * 0.70710678118654752f));
        *(__half2*)(Ch + (size_t)r * ldc + cn) = __floats2half2_rn(g0, g1);
    } else if (epi == 3) {
        Cf[(size_t)r * ldc + cn]     += v0;
        Cf[(size_t)r * ldc + cn + 1] += v1;
    } else if (epi == 5) {
        float u0 = v0 + bias[cn], u1 = v1 + bias[cn + 1];
        u0 = (u0 > 20.f) ? u0 : __logf(1.0f + __expf(u0));
        u1 = (u1 > 20.f) ? u1 : __logf(1.0f + __expf(u1));
        *(__half2*)(Ch + (size_t)r * ldc + cn) = __floats2half2_rn(u0, u1);
    } else if (epi == 6) {
        *(__half2*)(Ch + (size_t)r * ldc + cn) = __floats2half2_rn(v0, v1);
    } else { // 7
        int t = r & (TSEQ - 1), bidx = r >> 11;
        float o0 = Cf[(size_t)r * ldc + cn]     + v0 + bias[cn];
        float o1 = Cf[(size_t)r * ldc + cn + 1] + v1 + bias[cn + 1];
        if (t >= lenp[bidx]) { o0 = 0.f; o1 = 0.f; }
        Cf[(size_t)r * ldc + cn]     = o0;
        Cf[(size_t)r * ldc + cn + 1] = o1;
        if (out2) {
            out2[(size_t)r * ldc + cn]     = o0;
            out2[(size_t)r * ldc + cn + 1] = o1;
        }
    }
}

// ---------------- weight convert f32 -> f16 ---------------------------------
__global__ void k_round(const float* __restrict__ in, __half* __restrict__ out, int n4) {
    int i = blockIdx.x * 256 + threadIdx.x;
    if (i < n4) ((uint2*)out)[i] = cvt4(((const float4*)in)[i]);
}
__global__ void k_round5(
    const float* __restrict__ a, __half* __restrict__ oa, int na,
    const float* __restrict__ b, __half* __restrict__ ob, int nb,
    const float* __restrict__ c, __half* __restrict__ oc, int ncnt,
    const float* __restrict__ d, __half* __restrict__ od, int nd,
    const float* __restrict__ e, __half* __restrict__ oe, int ne) {
    int i = blockIdx.x * 256 + threadIdx.x;
    const float* s; __half* o;
    if (i < na) { s = a; o = oa; }
    else { i -= na;
      if (i < nb) { s = b; o = ob; }
      else { i -= nb;
        if (i < ncnt) { s = c; o = oc; }
        else { i -= ncnt;
          if (i < nd) { s = d; o = od; }
          else { i -= nd; if (i >= ne) return; s = e; o = oe; } } } }
    ((uint2*)o)[i] = cvt4(((const float4*)s)[i]);
}

// ---------------- block reduce ----------------------------------------------
__device__ __forceinline__ float blockReduce(float v, float* sh) {
    int lane = threadIdx.x & 31, wid = threadIdx.x >> 5;
    #pragma unroll
    for (int o = 16; o > 0; o >>= 1) v += __shfl_down_sync(0xffffffffu, v, o);
    if (lane == 0) sh[wid] = v;
    __syncthreads();
    if (threadIdx.x == 0) {
        float s = 0.f;
        #pragma unroll
        for (int i = 0; i < 8; i++) s += sh[i];
        sh[32] = s;
    }
    __syncthreads();
    float r = sh[32];
    __syncthreads();
    return r;
}

// ---------------- fused PE + ln0 + ln1(->half) --------------------------------
__global__ __launch_bounds__(256) void k_peln2(
    const float* __restrict__ xin, float* __restrict__ X, __half* __restrict__ Xn,
    const float* __restrict__ g0, const float* __restrict__ b0,
    const float* __restrict__ g1, const float* __restrict__ b1) {
    __shared__ float sh[33];
    int row = blockIdx.x;
    int t = row & (TSEQ - 1);
    int c = threadIdx.x * 4;
    float4 v = ((const float4*)(xin + (size_t)row * DM))[threadIdx.x];
    float pv[4];
    #pragma unroll
    for (int j = 0; j < 4; j++) {
        int d = c + j;
        float freq = expf((float)(d & ~1) * (-9.210340371976184f / (float)DM));
        float ang = (float)t * freq;
        pv[j] = (d & 1) ? cosf(ang) : sinf(ang);
    }
    v.x += pv[0]; v.y += pv[1]; v.z += pv[2]; v.w += pv[3];
    float mean = blockReduce(v.x + v.y + v.z + v.w, sh) * (1.0f / DM);
    float dx = v.x - mean, dy = v.y - mean, dz = v.z - mean, dw = v.w - mean;
    float var = blockReduce(dx*dx + dy*dy + dz*dz + dw*dw, sh) * (1.0f / DM);
    float rstd = rsqrtf(var + 1e-5f);
    float4 o;
    o.x = dx * rstd * g0[c + 0] + b0[c + 0];
    o.y = dy * rstd * g0[c + 1] + b0[c + 1];
    o.z = dz * rstd * g0[c + 2] + b0[c + 2];
    o.w = dw * rstd * g0[c + 3] + b0[c + 3];
    ((float4*)(X + (size_t)row * DM))[threadIdx.x] = o;
    float m2 = blockReduce(o.x + o.y + o.z + o.w, sh) * (1.0f / DM);
    float ex = o.x - m2, ey = o.y - m2, ez = o.z - m2, ew = o.w - m2;
    float v2 = blockReduce(ex*ex + ey*ey + ez*ez + ew*ew, sh) * (1.0f / DM);
    float r2 = rsqrtf(v2 + 1e-5f);
    float4 q;
    q.x = ex * r2 * g1[c + 0] + b1[c + 0];
    q.y = ey * r2 * g1[c + 1] + b1[c + 1];
    q.z = ez * r2 * g1[c + 2] + b1[c + 2];
    q.w = ew * r2 * g1[c + 3] + b1[c + 3];
    ((uint2*)(Xn + (size_t)row * DM))[threadIdx.x] = cvt4(q);
}

// ---------------- layernorm (fp32 in, half out) --------------------------------
__global__ __launch_bounds__(256) void k_ln_h(const float* __restrict__ in,
                                              __half* __restrict__ out,
                                              const float* __restrict__ g,
                                              const float* __restrict__ b) {
    __shared__ float sh[33];
    int row = blockIdx.x;
    float4 v = ((const float4*)(in + (size_t)row * DM))[threadIdx.x];
    float mean = blockReduce(v.x + v.y + v.z + v.w, sh) * (1.0f / DM);
    float dx = v.x - mean, dy = v.y - mean, dz = v.z - mean, dw = v.w - mean;
    float var = blockReduce(dx*dx + dy*dy + dz*dz + dw*dw, sh) * (1.0f / DM);
    float rstd = rsqrtf(var + 1e-5f);
    int c = threadIdx.x * 4;
    float4 q;
    q.x = dx * rstd * g[c + 0] + b[c + 0];
    q.y = dy * rstd * g[c + 1] + b[c + 1];
    q.z = dz * rstd * g[c + 2] + b[c + 2];
    q.w = dw * rstd * g[c + 3] + b[c + 3];
    ((uint2*)(out + (size_t)row * DM))[threadIdx.x] = cvt4(q);
}

// ---------------- GEMM kernel A: 128x128, 256 thr ----------------------------
#define SROWH 40
#define ABUF  (128 * SROWH * 2)
#define NSTG  5
#define SMEMA (2 * NSTG * ABUF)

__global__ __launch_bounds__(256, 2) void k_gemm_tc(
    const __half* __restrict__ A, const __half* __restrict__ W,
    float* __restrict__ Cf, __half* __restrict__ Ch, const float* __restrict__ bias,
    const int* __restrict__ lenp, float* __restrict__ out2,
    int N, int K, int lda, int ldw, int ldc, int epi) {
    extern __shared__ __half smh[];
    const int tid = threadIdx.x;
    const int lane = tid & 31;
    const int wid = tid >> 5;
    const int wm = wid & 1, wn = wid >> 1;
    const int g = lane >> 2, tig = lane & 3;
    const int bM = blockIdx.y * 128, bN = blockIdx.x * 128;

    const int lrow = tid >> 1;
    const int lc0 = (tid & 1) << 1;
    const __half* Ag = A + (size_t)(bM + lrow) * lda;
    int wr = bN + lrow; if (wr >= N) wr = N - 1;
    const __half* Wg = W + (size_t)wr * ldw;

    const uint32_t sA = (uint32_t)__cvta_generic_to_shared(smh);
    const uint32_t sB = sA + NSTG * ABUF;
    const uint32_t dRow = (uint32_t)lrow * (SROWH * 2);

    const uint32_t aoff = (uint32_t)((wm * 64 + (lane & 15)) * (SROWH * 2) + ((lane >> 4) << 4));
    const uint32_t boff = (uint32_t)((wn * 32 + ((lane >> 4) << 3) + (lane & 7)) * (SROWH * 2)
                                     + (((lane >> 3) & 1) << 4));

    float acc[4][4][4];
    #pragma unroll
    for (int i = 0; i < 4; i++)
        #pragma unroll
        for (int j = 0; j < 4; j++)
            #pragma unroll
            for (int q = 0; q < 4; q++) acc[i][j][q] = 0.f;

    const int KT = K / 32;
    #pragma unroll
    for (int s = 0; s < 3; s++) {
        if (s < KT) {
            const int k2 = s * 32;
            #pragma unroll
            for (int c = 0; c < 2; c++) {
                cpasync16(sA + s * ABUF + dRow + (lc0 + c) * 16, Ag + k2 + (lc0 + c) * 8);
                cpasync16(sB + s * ABUF + dRow + (lc0 + c) * 16, Wg + k2 + (lc0 + c) * 8);
            }
            asm volatile("cp.async.commit_group;");
        }
    }

    int s_r = 0, s_w = 3;
    for (int j = 0; j < KT; j++) {
        const int rem = KT - 1 - j;
        if (rem >= 3) {
            const int k2 = (j + 3) * 32;
            #pragma unroll
            for (int c = 0; c < 2; c++) {
                cpasync16(sA + s_w * ABUF + dRow + (lc0 + c) * 16, Ag + k2 + (lc0 + c) * 8);
                cpasync16(sB + s_w * ABUF + dRow + (lc0 + c) * 16, Wg + k2 + (lc0 + c) * 8);
            }
            asm volatile("cp.async.commit_group;");
            if (++s_w == NSTG) s_w = 0;
            asm volatile("cp.async.wait_group 3;");
        } else if (rem == 2) {
            asm volatile("cp.async.wait_group 2;");
        } else if (rem == 1) {
            asm volatile("cp.async.wait_group 1;");
        } else {
            asm volatile("cp.async.wait_group 0;");
        }
        __syncthreads();

        const uint32_t ab = sA + s_r * ABUF;
        const uint32_t bb = sB + s_r * ABUF;
        if (++s_r == NSTG) s_r = 0;
        #pragma unroll
        for (int ks = 0; ks < 2; ks++) {
            uint32_t af[4][4], bf[4][2];
            #pragma unroll
            for (int i = 0; i < 4; i++)
                LDSM4(af[i][0], af[i][1], af[i][2], af[i][3],
                      ab + aoff + (uint32_t)(i * 16 * SROWH * 2 + ks * 32));
            #pragma unroll
            for (int jp = 0; jp < 2; jp++)
                LDSM4(bf[2*jp][0], bf[2*jp][1], bf[2*jp+1][0], bf[2*jp+1][1],
                      bb + boff + (uint32_t)(jp * 16 * SROWH * 2 + ks * 32));
            #pragma unroll
            for (int i = 0; i < 4; i++)
                #pragma unroll
                for (int jj = 0; jj < 4; jj++)
                    mma_f16(acc[i][jj], af[i][0], af[i][1], af[i][2], af[i][3],
                            bf[jj][0], bf[jj][1]);
        }
    }

    #pragma unroll
    for (int i = 0; i < 4; i++) {
        const int r0 = bM + wm * 64 + i * 16 + g;
        #pragma unroll
        for (int j = 0; j < 4; j++) {
            const int cn = bN + wn * 32 + j * 8 + tig * 2;
            #pragma unroll
            for (int h = 0; h < 2; h++)
                epi_pair(acc[i][j][h*2], acc[i][j][h*2+1], r0 + h * 8, cn,
                         ldc, N, epi, Cf, Ch, bias, lenp, out2);
        }
    }
}

// ---------------- GEMM kernel B: 128x256, 512 thr (N % 256 == 0) -------------
#define ABUFA (128 * SROWH * 2)
#define ABUFB (256 * SROWH * 2)
#define NSTG2 5
#define SMEMB (NSTG2 * (ABUFA + ABUFB))

__global__ __launch_bounds__(512, 1) void k_gemm_tc2(
    const __half* __restrict__ A, const __half* __restrict__ W,
    float* __restrict__ Cf, __half* __restrict__ Ch, const float* __restrict__ bias,
    const int* __restrict__ lenp, float* __restrict__ out2,
    int N, int K, int lda, int ldw, int ldc, int epi) {
    extern __shared__ __half smh[];
    const int tid = threadIdx.x;
    const int lane = tid & 31;
    const int wid = tid >> 5;
    const int wm = wid & 1, wn = wid >> 1;
    const int g = lane >> 2, tig = lane & 3;
    const int bM = blockIdx.y * 128, bN = blockIdx.x * 256;

    const int lrA = tid >> 2, lcA = tid & 3;
    const __half* Ag = A + (size_t)(bM + lrA) * lda;
    const int lrB = tid >> 1, lcB = (tid & 1) << 1;
    const __half* Wg = W + (size_t)(bN + lrB) * ldw;

    const uint32_t sA = (uint32_t)__cvta_generic_to_shared(smh);
    const uint32_t sB = sA + NSTG2 * ABUFA;
    const uint32_t dRowA = (uint32_t)lrA * (SROWH * 2);
    const uint32_t dRowB = (uint32_t)lrB * (SROWH * 2);

    const uint32_t aoff = (uint32_t)((wm * 64 + (lane & 15)) * (SROWH * 2) + ((lane >> 4) << 4));
    const uint32_t boff = (uint32_t)((wn * 32 + ((lane >> 4) << 3) + (lane & 7)) * (SROWH * 2)
                                     + (((lane >> 3) & 1) << 4));

    float acc[4][4][4];
    #pragma unroll
    for (int i = 0; i < 4; i++)
        #pragma unroll
        for (int j = 0; j < 4; j++)
            #pragma unroll
            for (int q = 0; q < 4; q++) acc[i][j][q] = 0.f;

    const int KT = K / 32;
    #pragma unroll
    for (int s = 0; s < 3; s++) {
        if (s < KT) {
            const int k2 = s * 32;
            cpasync16(sA + s * ABUFA + dRowA + lcA * 16, Ag + k2 + lcA * 8);
            #pragma unroll
            for (int c = 0; c < 2; c++)
                cpasync16(sB + s * ABUFB + dRowB + (lcB + c) * 16, Wg + k2 + (lcB + c) * 8);
            asm volatile("cp.async.commit_group;");
        }
    }

    int s_r = 0, s_w = 3;
    for (int j = 0; j < KT; j++) {
        const int rem = KT - 1 - j;
        if (rem >= 3) {
            const int k2 = (j + 3) * 32;
            cpasync16(sA + s_w * ABUFA + dRowA + lcA * 16, Ag + k2 + lcA * 8);
            #pragma unroll
            for (int c = 0; c < 2; c++)
                cpasync16(sB + s_w * ABUFB + dRowB + (lcB + c) * 16, Wg + k2 + (lcB + c) * 8);
            asm volatile("cp.async.commit_group;");
            if (++s_w == NSTG2) s_w = 0;
            asm volatile("cp.async.wait_group 3;");
        } else if (rem == 2) {
            asm volatile("cp.async.wait_group 2;");
        } else if (rem == 1) {
            asm volatile("cp.async.wait_group 1;");
        } else {
            asm volatile("cp.async.wait_group 0;");
        }
        __syncthreads();

        const uint32_t ab = sA + s_r * ABUFA;
        const uint32_t bb = sB + s_r * ABUFB;
        if (++s_r == NSTG2) s_r = 0;
        #pragma unroll
        for (int ks = 0; ks < 2; ks++) {
            uint32_t af[4][4], bf[4][2];
            #pragma unroll
            for (int i = 0; i < 4; i++)
                LDSM4(af[i][0], af[i][1], af[i][2], af[i][3],
                      ab + aoff + (uint32_t)(i * 16 * SROWH * 2 + ks * 32));
            #pragma unroll
            for (int jp = 0; jp < 2; jp++)
                LDSM4(bf[2*jp][0], bf[2*jp][1], bf[2*jp+1][0], bf[2*jp+1][1],
                      bb + boff + (uint32_t)(jp * 16 * SROWH * 2 + ks * 32));
            #pragma unroll
            for (int i = 0; i < 4; i++)
                #pragma unroll
                for (int jj = 0; jj < 4; jj++)
                    mma_f16(acc[i][jj], af[i][0], af[i][1], af[i][2], af[i][3],
                            bf[jj][0], bf[jj][1]);
        }
    }

    #pragma unroll
    for (int i = 0; i < 4; i++) {
        const int r0 = bM + wm * 64 + i * 16 + g;
        #pragma unroll
        for (int j = 0; j < 4; j++) {
            const int cn = bN + wn * 32 + j * 8 + tig * 2;
            #pragma unroll
            for (int h = 0; h < 2; h++)
                epi_pair(acc[i][j][h*2], acc[i][j][h*2+1], r0 + h * 8, cn,
                         ldc, N, epi, Cf, Ch, bias, lenp, out2);
        }
    }
}

// ---------------- GEMM kernel C: 64x128, 256 thr (xp GEMM, N=96) -------------
// 8 warps (2x4) of 32x32 tiles; grid (1, MROWS/64) = 128 CTAs -> 128 SMs x 8 warps.
#define ABUF3A (64 * SROWH * 2)            // 5120 B
#define ABUF3B (128 * SROWH * 2)           // 10240 B
#define NSTG3  5
#define SMEMC  (NSTG3 * (ABUF3A + ABUF3B)) // 76800 B

__global__ __launch_bounds__(256, 2) void k_gemm_tc3(
    const __half* __restrict__ A, const __half* __restrict__ W,
    float* __restrict__ Cf, __half* __restrict__ Ch, const float* __restrict__ bias,
    const int* __restrict__ lenp, float* __restrict__ out2,
    int N, int K, int lda, int ldw, int ldc, int epi) {
    extern __shared__ __half smh[];
    const int tid = threadIdx.x;
    const int lane = tid & 31;
    const int wid = tid >> 5;                 // 0..7: 2(m) x 4(n), 32x32 tiles
    const int wm = wid & 1, wn = wid >> 1;
    const int g = lane >> 2, tig = lane & 3;
    const int bM = blockIdx.y * 64, bN = blockIdx.x * 128;

    // A loaders: 4 threads/row (64 rows), 1 chunk each
    const int lrA = tid >> 2, lcA = tid & 3;
    const __half* Ag = A + (size_t)(bM + lrA) * lda;
    // B loaders: 2 threads/row (128 rows), 2 chunks each
    const int lrB = tid >> 1, lcB = (tid & 1) << 1;
    int wr = bN + lrB; if (wr >= N) wr = N - 1;
    const __half* Wg = W + (size_t)wr * ldw;

    const uint32_t sA = (uint32_t)__cvta_generic_to_shared(smh);
    const uint32_t sB = sA + NSTG3 * ABUF3A;
    const uint32_t dRowA = (uint32_t)lrA * (SROWH * 2);
    const uint32_t dRowB = (uint32_t)lrB * (SROWH * 2);

    const uint32_t aoff = (uint32_t)((wm * 32 + (lane & 15)) * (SROWH * 2) + ((lane >> 4) << 4));
    const uint32_t boff = (uint32_t)((wn * 32 + ((lane >> 4) << 3) + (lane & 7)) * (SROWH * 2)
                                     + (((lane >> 3) & 1) << 4));

    float acc[2][4][4];
    #pragma unroll
    for (int i = 0; i < 2; i++)
        #pragma unroll
        for (int j = 0; j < 4; j++)
            #pragma unroll
            for (int q = 0; q < 4; q++) acc[i][j][q] = 0.f;

    const int KT = K / 32;
    #pragma unroll
    for (int s = 0; s < 3; s++) {
        if (s < KT) {
            const int k2 = s * 32;
            cpasync16(sA + s * ABUF3A + dRowA + lcA * 16, Ag + k2 + lcA * 8);
            #pragma unroll
            for (int c = 0; c < 2; c++)
                cpasync16(sB + s * ABUF3B + dRowB + (lcB + c) * 16, Wg + k2 + (lcB + c) * 8);
            asm volatile("cp.async.commit_group;");
        }
    }

    int s_r = 0, s_w = 3;
    for (int j = 0; j < KT; j++) {
        const int rem = KT - 1 - j;
        if (rem >= 3) {
            const int k2 = (j + 3) * 32;
            cpasync16(sA + s_w * ABUF3A + dRowA + lcA * 16, Ag + k2 + lcA * 8);
            #pragma unroll
            for (int c = 0; c < 2; c++)
                cpasync16(sB + s_w * ABUF3B + dRowB + (lcB + c) * 16, Wg + k2 + (lcB + c) * 8);
            asm volatile("cp.async.commit_group;");
            if (++s_w == NSTG3) s_w = 0;
            asm volatile("cp.async.wait_group 3;");
        } else if (rem == 2) {
            asm volatile("cp.async.wait_group 2;");
        } else if (rem == 1) {
            asm volatile("cp.async.wait_group 1;");
        } else {
            asm volatile("cp.async.wait_group 0;");
        }
        __syncthreads();

        const uint32_t ab = sA + s_r * ABUF3A;
        const uint32_t bb = sB + s_r * ABUF3B;
        if (++s_r == NSTG3) s_r = 0;
        #pragma unroll
        for (int ks = 0; ks < 2; ks++) {
            uint32_t af[2][4], bf[4][2];
            #pragma unroll
            for (int i = 0; i < 2; i++)
                LDSM4(af[i][0], af[i][1], af[i][2], af[i][3],
                      ab + aoff + (uint32_t)(i * 16 * SROWH * 2 + ks * 32));
            #pragma unroll
            for (int jp = 0; jp < 2; jp++)
                LDSM4(bf[2*jp][0], bf[2*jp][1], bf[2*jp+1][0], bf[2*jp+1][1],
                      bb + boff + (uint32_t)(jp * 16 * SROWH * 2 + ks * 32));
            #pragma unroll
            for (int i = 0; i < 2; i++)
                #pragma unroll
                for (int jj = 0; jj < 4; jj++)
                    mma_f16(acc[i][jj], af[i][0], af[i][1], af[i][2], af[i][3],
                            bf[jj][0], bf[jj][1]);
        }
    }

    #pragma unroll
    for (int i = 0; i < 2; i++) {
        const int r0 = bM + wm * 32 + i * 16 + g;
        #pragma unroll
        for (int j = 0; j < 4; j++) {
            const int cn = bN + wn * 32 + j * 8 + tig * 2;
            #pragma unroll
            for (int h = 0; h < 2; h++)
                epi_pair(acc[i][j][h*2], acc[i][j][h*2+1], r0 + h * 8, cn,
                         ldc, N, epi, Cf, Ch, bias, lenp, out2);
        }
    }
}

// ---------------- causal conv (k=4) + silu, 4 timesteps/thread ----------------
__global__ void k_conv(const __half* __restrict__ xz, const float* __restrict__ cw,
                       const float* __restrict__ cb, __half* __restrict__ xc) {
    int idx = blockIdx.x * 256 + threadIdx.x;
    int d2 = idx & (DI / 2 - 1);
    int mq = idx >> 10;
    int m0 = mq * 4;
    int t0 = m0 & (TSEQ - 1);
    int d = d2 * 2;
    float lo[7], hi[7];
    #pragma unroll
    for (int j = 0; j < 7; j++) {
        int tt = t0 - 3 + j;
        if (tt >= 0) {
            __half2 hv = *(const __half2*)(xz + (size_t)(m0 - 3 + j) * (2 * DI) + d);
            lo[j] = __low2float(hv); hi[j] = __high2float(hv);
        } else { lo[j] = 0.f; hi[j] = 0.f; }
    }
    float w0[4], w1[4];
    #pragma unroll
    for (int k = 0; k < 4; k++) { w0[k] = cw[d * 4 + k]; w1[k] = cw[(d + 1) * 4 + k]; }
    float b0 = cb[d], b1 = cb[d + 1];
    #pragma unroll
    for (int o = 0; o < 4; o++) {
        float a0 = b0, a1 = b1;
        #pragma unroll
        for (int k = 0; k < 4; k++) {
            a0 += lo[o + k] * w0[k];
            a1 += hi[o + k] * w1[k];
        }
        float s0 = a0 / (1.0f + __expf(-a0));
        float s1 = a1 / (1.0f + __expf(-a1));
        *(__half2*)(xc + (size_t)(m0 + o) * DI + d) = __floats2half2_rn(s0, s1);
    }
}

// ---------------- scan pass A -------------------------------------------------
__global__ __launch_bounds__(256) void k_scanA(
    const __half* __restrict__ dt, const __half* __restrict__ xc,
    const __half* __restrict__ xd, const float* __restrict__ Alog,
    float* __restrict__ gP, float* __restrict__ gS) {
    __shared__ float shB[CL][DS_];
    int b = blockIdx.z, c = blockIdx.y;
    int d = blockIdx.x * 256 + threadIdx.x;
    int mbase = b * TSEQ + c * CL;
    for (int idx = threadIdx.x; idx < CL * DS_; idx += 256) {
        int t = idx >> 4, col = idx & 15;
        shB[t][col] = __half2float(xd[(size_t)(mbase + t) * 96 + 64 + col]);
    }
    __syncthreads();
    float r[DS_];
    bool fast = true;
    #pragma unroll
    for (int n = 0; n < DS_; n++) {
        r[n] = expf(Alog[(size_t)d * DS_ + n]);
        fast = fast && (fabsf(r[n] - (float)(n + 1)) < 1e-3f * (float)(n + 1));
    }
    float P[DS_], S[DS_];
    #pragma unroll
    for (int n = 0; n < DS_; n++) { P[n] = 1.f; S[n] = 0.f; }
    for (int t = 0; t < CL; t++) {
        int m = mbase + t;
        float dv = __half2float(dt[(size_t)m * DI + d]);
        float xv = __half2float(xc[(size_t)m * DI + d]);
        float u = xv * dv;
        float dA[DS_];
        if (fast) {
            float e = __expf(-dv);
            float p = 1.f;
            #pragma unroll
            for (int n = 0; n < DS_; n++) { p *= e; dA[n] = p; }
        } else {
            #pragma unroll
            for (int n = 0; n < DS_; n++) dA[n] = __expf(-dv * r[n]);
        }
        #pragma unroll
        for (int n = 0; n < DS_; n++) {
            S[n] = S[n] * dA[n] + u * shB[t][n];
            P[n] *= dA[n];
        }
    }
    size_t base = (((size_t)b * NC + c) * DI + d) * DS_;
    #pragma unroll
    for (int n = 0; n < DS_; n += 4) {
        *(float4*)(gP + base + n) = make_float4(P[n], P[n+1], P[n+2], P[n+3]);
        *(float4*)(gS + base + n) = make_float4(S[n], S[n+1], S[n+2], S[n+3]);
    }
}

// ---------------- scan pass B (parallel over 4-state quads) -------------------
__global__ void k_scanB(const float* __restrict__ gP, const float* __restrict__ gS,
                        float* __restrict__ gI) {
    int idx = blockIdx.x * 256 + threadIdx.x;
    int nq = (idx & 3) * 4;
    int d  = (idx >> 2) & (DI - 1);
    int b  = idx >> 13;
    float4 s = make_float4(0.f, 0.f, 0.f, 0.f);
    for (int c = 0; c < NC; c++) {
        size_t base = (((size_t)b * NC + c) * DI + d) * DS_ + nq;
        *(float4*)(gI + base) = s;
        float4 P = *(const float4*)(gP + base);
        float4 S = *(const float4*)(gS + base);
        s.x = s.x * P.x + S.x;
        s.y = s.y * P.y + S.y;
        s.z = s.z * P.z + S.z;
        s.w = s.w * P.w + S.w;
    }
}

// ---------------- scan pass C -------------------------------------------------
__global__ __launch_bounds__(256) void k_scanC(
    const __half* __restrict__ dt, const __half* __restrict__ xc,
    const __half* __restrict__ xd, const __half* __restrict__ xz,
    const float* __restrict__ Alog, const float* __restrict__ Dsk,
    const float* __restrict__ gI, __half* __restrict__ ym) {
    __shared__ float shB[CL][DS_];
    __shared__ float shC[CL][DS_];
    int b = blockIdx.z, c = blockIdx.y;
    int d = blockIdx.x * 256 + threadIdx.x;
    int mbase = b * TSEQ + c * CL;
    for (int idx = threadIdx.x; idx < CL * 32; idx += 256) {
        int t = idx >> 5, col = idx & 31;
        float v = __half2float(xd[(size_t)(mbase + t) * 96 + 64 + col]);
        if (col < 16) shB[t][col] = v;
        else shC[t][col - 16] = v;
    }
    __syncthreads();
    float r[DS_];
    bool fast = true;
    #pragma unroll
    for (int n = 0; n < DS_; n++) {
        r[n] = expf(Alog[(size_t)d * DS_ + n]);
        fast = fast && (fabsf(r[n] - (float)(n + 1)) < 1e-3f * (float)(n + 1));
    }
    float dskip = Dsk[d];
    float s[DS_];
    size_t base = (((size_t)b * NC + c) * DI + d) * DS_;
    #pragma unroll
    for (int n = 0; n < DS_; n += 4) {
        float4 v = *(const float4*)(gI + base + n);
        s[n+0] = v.x; s[n+1] = v.y; s[n+2] = v.z; s[n+3] = v.w;
    }
    for (int t = 0; t < CL; t++) {
        int m = mbase + t;
        float dv = __half2float(dt[(size_t)m * DI + d]);
        float xv = __half2float(xc[(size_t)m * DI + d]);
        float u = xv * dv;
        float dA[DS_];
        if (fast) {
            float e = __expf(-dv);
            float p = 1.f;
            #pragma unroll
            for (int n = 0; n < DS_; n++) { p *= e; dA[n] = p; }
        } else {
            #pragma unroll
            for (int n = 0; n < DS_; n++) dA[n] = __expf(-dv * r[n]);
        }
        float y = 0.f;
        #pragma unroll
        for (int n = 0; n < DS_; n++) {
            s[n] = s[n] * dA[n] + u * shB[t][n];
            y += s[n] * shC[t][n];
        }
        float z = __half2float(xz[(size_t)m * (2 * DI) + DI + d]);
        float sg = 1.0f / (1.0f + __expf(-z));
        ym[(size_t)m * DI + d] = __float2half_rn((y + dskip * xv) * (z * sg));
    }
}

// ---------------- host orchestration -------------------------------------------
static void launch_gemm(const __half* A, const __half* W,
                        float* Cf, __half* Ch, const float* bias,
                        const int* lenp, float* out2,
                        int N, int K, int lda, int ldc, int epi) {
    if ((N & 255) == 0) {
        dim3 grid(N / 256, MROWS / 128);
        k_gemm_tc2<<<grid, 512, SMEMB>>>(A, W, Cf, Ch, bias, lenp, out2, N, K, lda, K, ldc, epi);
    } else if (N <= 128) {
        dim3 grid(1, MROWS / 64);
        k_gemm_tc3<<<grid, 256, SMEMC>>>(A, W, Cf, Ch, bias, lenp, out2, N, K, lda, K, ldc, epi);
    } else {
        dim3 grid((N + 127) / 128, MROWS / 128);
        k_gemm_tc<<<grid, 256, SMEMA>>>(A, W, Cf, Ch, bias, lenp, out2, N, K, lda, K, ldc, epi);
    }
}

extern "C" void kernel_launch(void* const* d_in, const int* in_sizes, int n_in,
                              void* d_out, int out_size) {
    const float* x       = (const float*)d_in[0];
    const int*   lengths = (const int*)  d_in[1];
    const float* ln0_g   = (const float*)d_in[2];
    const float* ln0_b   = (const float*)d_in[3];
    const float* ln1_g   = (const float*)d_in[4];
    const float* ln1_b   = (const float*)d_in[5];
    const float* in_w    = (const float*)d_in[6];
    const float* conv_w  = (const float*)d_in[7];
    const float* conv_b  = (const float*)d_in[8];
    const float* xp_w    = (const float*)d_in[9];
    const float* dt_w    = (const float*)d_in[10];
    const float* dt_b    = (const float*)d_in[11];
    const float* A_log   = (const float*)d_in[12];
    const float* D_skip  = (const float*)d_in[13];
    const float* out_w   = (const float*)d_in[14];
    const float* ln2_g   = (const float*)d_in[15];
    const float* ln2_b   = (const float*)d_in[16];
    const float* f1_w    = (const float*)d_in[17];
    const float* f1_b    = (const float*)d_in[18];
    const float* f2_w    = (const float*)d_in[19];
    const float* f2_b    = (const float*)d_in[20];

    cudaFuncSetAttribute(k_gemm_tc,  cudaFuncAttributeMaxDynamicSharedMemorySize, SMEMA);
    cudaFuncSetAttribute(k_gemm_tc2, cudaFuncAttributeMaxDynamicSharedMemorySize, SMEMB);
    cudaFuncSetAttribute(k_gemm_tc3, cudaFuncAttributeMaxDynamicSharedMemorySize, SMEMC);

    float *pX, *pP, *pS, *pI;
    __half *pXn, *pXz, *pXc, *pXd, *pDt, *pY, *pF, *pWa;
    cudaGetSymbolAddress((void**)&pX,  g_X);
    cudaGetSymbolAddress((void**)&pXn, g_Xn);
    cudaGetSymbolAddress((void**)&pXz, g_xz);
    cudaGetSymbolAddress((void**)&pXc, g_xc);
    cudaGetSymbolAddress((void**)&pXd, g_xd);
    cudaGetSymbolAddress((void**)&pDt, g_dt);
    cudaGetSymbolAddress((void**)&pY,  g_ym);
    cudaGetSymbolAddress((void**)&pF,  g_ffn);
    cudaGetSymbolAddress((void**)&pP,  g_cP);
    cudaGetSymbolAddress((void**)&pS,  g_cS);
    cudaGetSymbolAddress((void**)&pI,  g_cI);
    cudaGetSymbolAddress((void**)&pWa, g_wa);

    // [1] in_proj weights
    k_round<<<(SZ_IN / 4 + 255) / 256, 256>>>(in_w, pWa + OW_IN, SZ_IN / 4);
    // [2] remaining weights, one packed launch
    {
        int na = SZ_XP / 4, nb = SZ_DT / 4, nc2 = SZ_OUT / 4, nd = SZ_F1 / 4, ne = SZ_F2 / 4;
        int tot = na + nb + nc2 + nd + ne;
        k_round5<<<(tot + 255) / 256, 256>>>(
            xp_w,  pWa + OW_XP,  na,
            dt_w,  pWa + OW_DT,  nb,
            out_w, pWa + OW_OUT, nc2,
            f1_w,  pWa + OW_F1,  nd,
            f2_w,  pWa + OW_F2,  ne);
    }
    // [3] fused PE + ln0 + ln1(layer0)
    k_peln2<<<MROWS, 256>>>(x, pX, pXn, ln0_g, ln0_b, ln1_g, ln1_b);

    for (int i = 0; i < 4; i++) {
        // --- Mamba block ---
        if (i > 0)
            k_ln_h<<<MROWS, 256>>>(pX, pXn, ln1_g + i * DM, ln1_b + i * DM);
        // [4] in_proj GEMM (ncu capture slot)
        launch_gemm(pXn, pWa + OW_IN + (size_t)i * 2 * DI * DM, nullptr, pXz, nullptr,
                    nullptr, nullptr, 2 * DI, DM, DM, 2 * DI, 6);
        k_conv<<<(MROWS / 4) * (DI / 2) / 256, 256>>>(pXz, conv_w + (size_t)i * DI * 4,
                                                      conv_b + (size_t)i * DI, pXc);
        launch_gemm(pXc, pWa + OW_XP + (size_t)i * 96 * DI, nullptr, pXd, nullptr,
                    nullptr, nullptr, 96, DI, DI, 96, 6);
        launch_gemm(pXd, pWa + OW_DT + (size_t)i * DI * DTR, nullptr, pDt,
                    dt_b + (size_t)i * DI, nullptr, nullptr, DI, DTR, 96, DI, 5);
        dim3 sg(DI / 256, NC, BB);
        k_scanA<<<sg, 256>>>(pDt, pXc, pXd, A_log + (size_t)i * DI * DS_, pP, pS);
        k_scanB<<<(BB * DI * 4) / 256, 256>>>(pP, pS, pI);
        k_scanC<<<sg, 256>>>(pDt, pXc, pXd, pXz, A_log + (size_t)i * DI * DS_,
                             D_skip + (size_t)i * DI, pI, pY);
        launch_gemm(pY, pWa + OW_OUT + (size_t)i * DM * DI, pX, nullptr, nullptr,
                    nullptr, nullptr, DM, DI, DI, DM, 3);
        // --- FFN block ---
        k_ln_h<<<MROWS, 256>>>(pX, pXn, ln2_g + i * DM, ln2_b + i * DM);
        launch_gemm(pXn, pWa + OW_F1 + (size_t)i * FFND * DM, nullptr, pF,
                    f1_b + (size_t)i * FFND, nullptr, nullptr, FFND, DM, DM, FFND, 2);
        launch_gemm(pF, pWa + OW_F2 + (size_t)i * DM * FFND, pX, nullptr,
                    f2_b + (size_t)i * DM, lengths,
                    (i == 3) ? (float*)d_out : nullptr, DM, FFND, FFND, DM, 7);
    }
}